// round 14
// baseline (speedup 1.0000x reference)
#include <cuda_runtime.h>

#define ENC_LEVELS 80
#define NPAIRS     (ENC_LEVELS / 2)   // 40 float4 per position

// ---------------------------------------------------------------------------
// Compile-time tables. For v = m * 2^(Ev-150) (fp32 bits):
//   frac(v / 2pi) = frac(m * frac(2^(Ev-150) / 2pi))
// T[Ev] = frac(2^(Ev-150)/2pi) in 2^-64 fixed point, from the bits of 2/pi.
// ---------------------------------------------------------------------------
namespace petab {

constexpr unsigned int TP[12] = {   // fdlibm two_over_pi, 24-bit chunks
    0xA2F983, 0x6E4E44, 0x1529FC, 0x2757D1, 0xF534DD, 0xC0DB62,
    0x95993C, 0x439041, 0xFE5163, 0xABDEBB, 0xC561B7, 0x246E3A
};

constexpr int tp_bit(int i) {       // bit i (1-indexed) of frac(2/pi)
    if (i < 1 || i > 12 * 24) return 0;
    int c = (i - 1) / 24, b = (i - 1) % 24;
    return (int)((TP[c] >> (23 - b)) & 1u);
}

constexpr unsigned long long make_T(int ev) {
    int k = ev - 150;
    unsigned long long t = 0;
    for (int j = 0; j < 64; j++)
        t = (t << 1) | (unsigned long long)tp_bit(k - 1 + j);
    t += (unsigned long long)tp_bit(k + 63);   // round (mod-2^64 wrap ok)
    return t;
}

constexpr double pow125(int i) {
    double b = 1.25, s = 1.0;
    while (i) { if (i & 1) s *= b; b *= b; i >>= 1; }
    return s;
}

struct Tables {
    unsigned long long T[256];
    float S[ENC_LEVELS];
    constexpr Tables() : T(), S() {
        for (int e = 0; e < 256; e++) T[e] = make_T(e);
        for (int i = 0; i < ENC_LEVELS; i++)
            S[i] = (float)pow125(i) * 3.14159265358979323846f;  // * fl32(pi)
    }
};

} // namespace petab

__device__ constexpr petab::Tables g_tab = petab::Tables();

#define TWO_PI_F 6.28318530717958647692f

// (sin, cos) of v = fl32(pf*s) via exponent-table fixed-point reduction.
__device__ __forceinline__ float2 pe_pair(float pf, float s,
                                          const unsigned long long* __restrict__ sT) {
    float v = __fmul_rn(pf, s);
    unsigned int iv = __float_as_uint(v);
    unsigned long long T = sT[iv >> 23];                    // LDS.64
    unsigned int m   = (iv & 0x7FFFFFu) | 0x800000u;        // 24-bit mantissa
    unsigned int Tlo = (unsigned int)T;
    unsigned int Thi = (unsigned int)(T >> 32);
    unsigned int h = __umulhi(m, Tlo) + m * Thi + 0x80000000u;  // +0.5 turn center
    float uf = __uint_as_float(0x3F800000u | (h >> 9));     // 1 + frac'
    float theta = (uf - 1.5f) * TWO_PI_F;                   // [-pi, pi)
    float2 sc;
    sc.x = __sinf(theta);                                   // MUFU.SIN
    sc.y = __cosf(theta);                                   // MUFU.COS
    return sc;
}

// One quad (float4) = levels (2x, 2x+1) of position p, where q = p*40 + x.
__device__ __forceinline__ float4 pe_quad(unsigned int q,
                                          const unsigned long long* __restrict__ sT,
                                          const float2* __restrict__ sS) {
    unsigned int p = q / 40u;          // UMULHI magic
    unsigned int x = q - p * 40u;
    float pf = (float)p;               // exact: p < 2^24
    float2 s = sS[x];                  // LDS.64
    float2 a = pe_pair(pf, s.x, sT);
    float2 b = pe_pair(pf, s.y, sT);
    float4 r; r.x = a.x; r.y = a.y; r.z = b.x; r.w = b.y;
    return r;
}

// R13 best config + single-variable change: evict-first streaming stores
// (__stcs). Flat mapping, 256-thread blocks, 8 blocks/SM = 64 warps, one
// balanced wave; 4 independent quads + 4 batched STG.128 per iteration.
__global__ void __launch_bounds__(256, 8) pe_main_kernel(float4* __restrict__ out,
                                                         unsigned int nq) {
    __shared__ unsigned long long sT[256];
    __shared__ float2 sS[NPAIRS];
    int t = threadIdx.x;
    sT[t] = g_tab.T[t];
    if (t < NPAIRS) sS[t] = make_float2(g_tab.S[2 * t], g_tab.S[2 * t + 1]);
    __syncthreads();

    unsigned int q      = blockIdx.x * 1024u + (unsigned int)t;
    unsigned int stride = gridDim.x * 1024u;

    for (; q < nq; q += stride) {
        unsigned int q1 = q + 256u, q2 = q + 512u, q3 = q + 768u;
        if (q3 < nq) {                       // fast path: all 4 valid
            float4 r0 = pe_quad(q,  sT, sS);
            float4 r1 = pe_quad(q1, sT, sS);
            float4 r2 = pe_quad(q2, sT, sS);
            float4 r3 = pe_quad(q3, sT, sS);
            __stcs(out + q,  r0);            // evict-first streaming stores
            __stcs(out + q1, r1);
            __stcs(out + q2, r2);
            __stcs(out + q3, r3);
        } else {                             // tail
            __stcs(out + q, pe_quad(q, sT, sS));
            if (q1 < nq) __stcs(out + q1, pe_quad(q1, sT, sS));
            if (q2 < nq) __stcs(out + q2, pe_quad(q2, sT, sS));
        }
    }
}

extern "C" void kernel_launch(void* const* d_in, const int* in_sizes, int n_in,
                              void* d_out, int out_size) {
    (void)d_in; (void)n_in; (void)out_size;  // reference ignores pos values
    unsigned int n  = (unsigned int)in_sizes[0];
    unsigned int nq = n * (unsigned int)NPAIRS;   // total float4 quads (20M)

    int blocks = 148 * 8;                    // 64/64 warps per SM, one wave
    unsigned int max_needed = (nq + 1023u) / 1024u;
    if ((unsigned int)blocks > max_needed) blocks = (int)max_needed;
    if (blocks < 1) blocks = 1;
    pe_main_kernel<<<blocks, 256>>>((float4*)d_out, nq);
}

// round 15
// speedup vs baseline: 1.0054x; 1.0054x over previous
#include <cuda_runtime.h>

#define ENC_LEVELS 80
#define NPAIRS     (ENC_LEVELS / 2)   // 40 float4 per position

// ---------------------------------------------------------------------------
// Compile-time tables. For v = m * 2^(Ev-150) (fp32 bits):
//   frac(v / 2pi) = frac(m * frac(2^(Ev-150) / 2pi))
// T[Ev] = frac(2^(Ev-150)/2pi) in 2^-64 fixed point, from the bits of 2/pi.
// ---------------------------------------------------------------------------
namespace petab {

constexpr unsigned int TP[12] = {   // fdlibm two_over_pi, 24-bit chunks
    0xA2F983, 0x6E4E44, 0x1529FC, 0x2757D1, 0xF534DD, 0xC0DB62,
    0x95993C, 0x439041, 0xFE5163, 0xABDEBB, 0xC561B7, 0x246E3A
};

constexpr int tp_bit(int i) {       // bit i (1-indexed) of frac(2/pi)
    if (i < 1 || i > 12 * 24) return 0;
    int c = (i - 1) / 24, b = (i - 1) % 24;
    return (int)((TP[c] >> (23 - b)) & 1u);
}

constexpr unsigned long long make_T(int ev) {
    int k = ev - 150;
    unsigned long long t = 0;
    for (int j = 0; j < 64; j++)
        t = (t << 1) | (unsigned long long)tp_bit(k - 1 + j);
    t += (unsigned long long)tp_bit(k + 63);   // round (mod-2^64 wrap ok)
    return t;
}

constexpr double pow125(int i) {
    double b = 1.25, s = 1.0;
    while (i) { if (i & 1) s *= b; b *= b; i >>= 1; }
    return s;
}

struct Tables {
    unsigned long long T[256];
    float S[ENC_LEVELS];
    constexpr Tables() : T(), S() {
        for (int e = 0; e < 256; e++) T[e] = make_T(e);
        for (int i = 0; i < ENC_LEVELS; i++)
            S[i] = (float)pow125(i) * 3.14159265358979323846f;  // * fl32(pi)
    }
};

} // namespace petab

__device__ constexpr petab::Tables g_tab = petab::Tables();

#define TWO_PI_F 6.28318530717958647692f

// (sin, cos) of v = fl32(pf*s) via exponent-table fixed-point reduction.
__device__ __forceinline__ float2 pe_pair(float pf, float s,
                                          const unsigned long long* __restrict__ sT) {
    float v = __fmul_rn(pf, s);
    unsigned int iv = __float_as_uint(v);
    unsigned long long T = sT[iv >> 23];                    // LDS.64
    unsigned int m   = (iv & 0x7FFFFFu) | 0x800000u;        // 24-bit mantissa
    unsigned int Tlo = (unsigned int)T;
    unsigned int Thi = (unsigned int)(T >> 32);
    unsigned int h = __umulhi(m, Tlo) + m * Thi + 0x80000000u;  // +0.5 turn center
    float uf = __uint_as_float(0x3F800000u | (h >> 9));     // 1 + frac'
    float theta = (uf - 1.5f) * TWO_PI_F;                   // [-pi, pi)
    float2 sc;
    sc.x = __sinf(theta);                                   // MUFU.SIN
    sc.y = __cosf(theta);                                   // MUFU.COS
    return sc;
}

// One quad (float4) = levels (2x, 2x+1) of position p, where q = p*40 + x.
__device__ __forceinline__ float4 pe_quad(unsigned int q,
                                          const unsigned long long* __restrict__ sT,
                                          const float2* __restrict__ sS) {
    unsigned int p = q / 40u;          // UMULHI magic
    unsigned int x = q - p * 40u;
    float pf = (float)p;               // exact: p < 2^24
    float2 s = sS[x];                  // LDS.64
    float2 a = pe_pair(pf, s.x, sT);
    float2 b = pe_pair(pf, s.y, sT);
    float4 r; r.x = a.x; r.y = a.y; r.z = b.x; r.w = b.y;
    return r;
}

// Final configuration (best measured, R13): flat mapping, 256-thread blocks,
// 8 blocks/SM = 64 warps resident, one balanced wave. Each thread covers
// quads q, q+256, q+512, q+768 per grid-stride iteration — 4 independent
// chains, 4 batched warp-contiguous STG.128. Measured at the GB300
// pure-write drain ceiling (~6.6 TB/s actual).
__global__ void __launch_bounds__(256, 8) pe_main_kernel(float4* __restrict__ out,
                                                         unsigned int nq) {
    __shared__ unsigned long long sT[256];
    __shared__ float2 sS[NPAIRS];
    int t = threadIdx.x;
    sT[t] = g_tab.T[t];
    if (t < NPAIRS) sS[t] = make_float2(g_tab.S[2 * t], g_tab.S[2 * t + 1]);
    __syncthreads();

    unsigned int q      = blockIdx.x * 1024u + (unsigned int)t;
    unsigned int stride = gridDim.x * 1024u;

    for (; q < nq; q += stride) {
        unsigned int q1 = q + 256u, q2 = q + 512u, q3 = q + 768u;
        if (q3 < nq) {                       // fast path: all 4 valid
            float4 r0 = pe_quad(q,  sT, sS);
            float4 r1 = pe_quad(q1, sT, sS);
            float4 r2 = pe_quad(q2, sT, sS);
            float4 r3 = pe_quad(q3, sT, sS);
            out[q]  = r0;
            out[q1] = r1;
            out[q2] = r2;
            out[q3] = r3;
        } else {                             // tail
            out[q] = pe_quad(q, sT, sS);
            if (q1 < nq) out[q1] = pe_quad(q1, sT, sS);
            if (q2 < nq) out[q2] = pe_quad(q2, sT, sS);
        }
    }
}

extern "C" void kernel_launch(void* const* d_in, const int* in_sizes, int n_in,
                              void* d_out, int out_size) {
    (void)d_in; (void)n_in; (void)out_size;  // reference ignores pos values
    unsigned int n  = (unsigned int)in_sizes[0];
    unsigned int nq = n * (unsigned int)NPAIRS;   // total float4 quads (20M)

    int blocks = 148 * 8;                    // 64/64 warps per SM, one wave
    unsigned int max_needed = (nq + 1023u) / 1024u;
    if ((unsigned int)blocks > max_needed) blocks = (int)max_needed;
    if (blocks < 1) blocks = 1;
    pe_main_kernel<<<blocks, 256>>>((float4*)d_out, nq);
}